// round 13
// baseline (speedup 1.0000x reference)
#include <cuda_runtime.h>
#include <cuda_fp16.h>
#include <stdint.h>

#define K_DIM 4096
#define N_DIM 4096
#define M_DIM 8192

#define BM 128
#define BN 128
#define BK 64                 // fp16 per k-step = 128B row
#define NSEG_KT 64            // k-steps per segment
#define NKT 128               // 2 segments: Xh*Wl (f16acc), Xh*Wh (f32acc)
#define NTHREADS 256
#define STAGES 3
#define A_BYTES (BM * 128)    // 16384
#define B_BYTES (BN * 128)    // 16384
#define STAGE_BYTES (A_BYTES + B_BYTES)   // 32768
#define SMEM_DYN (STAGES * STAGE_BYTES + 256)

typedef unsigned long long u64;

// ---- device scratch (allocation-guard-safe) --------------------------------
__device__ __half g_xh[(size_t)M_DIM * K_DIM];
__device__ __half g_wh[(size_t)N_DIM * K_DIM];  // [n][k] : Weff^T hi
__device__ __half g_wl[(size_t)N_DIM * K_DIM];  // [n][k] : Weff^T residual

__device__ __forceinline__ uint32_t smem_to_u32(const void* p) {
    uint32_t a;
    asm("{ .reg .u64 t; cvta.to.shared.u64 t, %1; cvt.u32.u64 %0, t; }"
        : "=r"(a) : "l"(p));
    return a;
}
__device__ __forceinline__ void cp16(uint32_t dst, const void* src) {
    asm volatile("cp.async.cg.shared.global [%0], [%1], 16;\n" :: "r"(dst), "l"(src));
}
#define CP_COMMIT() asm volatile("cp.async.commit_group;\n" ::: "memory")
#define CP_WAIT(n) asm volatile("cp.async.wait_group %0;\n" :: "n"(n) : "memory")

__device__ __forceinline__ void ldsm_x4(uint32_t (&r)[4], uint32_t addr) {
    asm volatile("ldmatrix.sync.aligned.m8n8.x4.shared.b16 {%0,%1,%2,%3}, [%4];"
                 : "=r"(r[0]), "=r"(r[1]), "=r"(r[2]), "=r"(r[3]) : "r"(addr));
}
// fp32-accum HMMA (main term)
__device__ __forceinline__ void mma_f32acc(float (&c)[4], const uint32_t (&a)[4],
                                           uint32_t b0, uint32_t b1) {
    asm volatile(
        "mma.sync.aligned.m16n8k16.row.col.f32.f16.f16.f32 "
        "{%0,%1,%2,%3}, {%4,%5,%6,%7}, {%8,%9}, {%0,%1,%2,%3};"
        : "+f"(c[0]), "+f"(c[1]), "+f"(c[2]), "+f"(c[3])
        : "r"(a[0]), "r"(a[1]), "r"(a[2]), "r"(a[3]), "r"(b0), "r"(b1));
}
// fp16-accum HMMA (correction term; values ~1e-3, precision ample)
__device__ __forceinline__ void mma_f16acc(uint32_t (&c)[2], const uint32_t (&a)[4],
                                           uint32_t b0, uint32_t b1) {
    asm volatile(
        "mma.sync.aligned.m16n8k16.row.col.f16.f16.f16.f16 "
        "{%0,%1}, {%2,%3,%4,%5}, {%6,%7}, {%0,%1};"
        : "+r"(c[0]), "+r"(c[1])
        : "r"(a[0]), "r"(a[1]), "r"(a[2]), "r"(a[3]), "r"(b0), "r"(b1));
}

// ---------------------------------------------------------------------------
// merged prep: grid.y==0 -> convert X to fp16 hi; grid.y==1 -> build W splits
// ---------------------------------------------------------------------------
__global__ void prep_kernel(const float* __restrict__ x,
                            const float* __restrict__ w,
                            const float* __restrict__ la,
                            const float* __restrict__ lb) {
    __shared__ float as_[32][17];
    __shared__ float bs_[16][33];
    const int tid = threadIdx.x;

    if (blockIdx.y == 0) {
        // ---- convert X -> fp16 hi only ----
        size_t i = ((size_t)blockIdx.x * 256 + tid) * 8;
        float4 a = *(const float4*)(x + i);
        float4 b = *(const float4*)(x + i + 4);
        float v[8] = {a.x, a.y, a.z, a.w, b.x, b.y, b.z, b.w};
        union { __half h[8]; uint4 u; } H;
#pragma unroll
        for (int j = 0; j < 8; j++) H.h[j] = __float2half(v[j]);
        *(uint4*)(g_xh + i) = H.u;
        return;
    }

    // ---- build Wt[n][k] = W[n][k] + 2*sum_r A[k][r]*B[r][n], split hi/lo ----
    const int k0 = (blockIdx.x & 127) * 32;
    const int n0 = (blockIdx.x >> 7) * 32;
    const int tx = tid & 31;   // k_local
    const int ty = tid >> 5;   // 0..7
    for (int i = tid; i < 512; i += 256) {
        int kk = i >> 4, r = i & 15;
        as_[kk][r] = la[(size_t)(k0 + kk) * 16 + r];
    }
    for (int i = tid; i < 512; i += 256) {
        int r = i >> 5, nn = i & 31;
        bs_[r][nn] = lb[(size_t)r * N_DIM + (n0 + nn)];
    }
    __syncthreads();
#pragma unroll
    for (int i = 0; i < 4; i++) {
        int nl = ty + i * 8;
        float s = 0.f;
#pragma unroll
        for (int r = 0; r < 16; r++) s += as_[tx][r] * bs_[r][nl];
        size_t idx = (size_t)(n0 + nl) * K_DIM + k0 + tx;
        float val = w[idx] + 2.0f * s;
        __half h = __float2half(val);
        g_wh[idx] = h;
        g_wl[idx] = __float2half(val - __half2float(h));
    }
}

// ---------------------------------------------------------------------------
// HMMA GEMM: C = Xh@Wl^T (f16 acc) + Xh@Wh^T (f32 acc) + bias
// CTA tile 128x128, 8 warps (2m x 4n), warp tile 64x32, 3-stage pipeline,
// 2 CTAs/SM so barrier bubbles of co-resident CTAs interleave.
// ---------------------------------------------------------------------------
__global__ void __launch_bounds__(NTHREADS, 2)
gemm_hmma_kernel(const float* __restrict__ bias, float* __restrict__ C) {
    extern __shared__ char smraw[];
    const uint32_t sb = (smem_to_u32(smraw) + 127u) & ~127u;

    const int tid = threadIdx.x;
    const int wid = tid >> 5;
    const int lid = tid & 31;
    const int wm = wid & 1;        // 0..1 -> 64-row slab
    const int wn = wid >> 1;       // 0..3 -> 32-col slab
    const int bm = blockIdx.y * BM;
    const int bn = blockIdx.x * BN;

    uint32_t acc_h[4][4][2];       // f16x2 accum for correction term
#pragma unroll
    for (int i = 0; i < 4; i++)
#pragma unroll
        for (int j = 0; j < 4; j++) { acc_h[i][j][0] = 0u; acc_h[i][j][1] = 0u; }
    float acc_f[4][4][4];          // f32 accum (initialized at segment switch)

    // ---- loader geometry: thread t handles chunks c = t + 256*i ----
    const int arow = tid >> 3;             // 0..31
    const int ach = tid & 7;               // chunk in 128B row
    const size_t Kb = (size_t)K_DIM * 2;   // row stride bytes
    const uint32_t dsw = (uint32_t)((ach ^ (arow & 7)) * 16);
    const uint32_t a_dst = sb + (uint32_t)arow * 128u + dsw;            // +4096*i
    const uint32_t b_dst = sb + A_BYTES + (uint32_t)arow * 128u + dsw;  // +4096*i

    const char* xh_p = (const char*)g_xh + (size_t)(bm + arow) * Kb + (size_t)ach * 16;
    const char* wh_p = (const char*)g_wh + (size_t)(bn + arow) * Kb + (size_t)ach * 16;
    const char* wl_p = (const char*)g_wl + (size_t)(bn + arow) * Kb + (size_t)ach * 16;
    const size_t gstride = 32 * Kb;        // +32 rows

    // segment order: 0: Xh*Wl (f16 acc), 1: Xh*Wh (f32 acc)
    auto load_stage = [&](int s, int kt) {
        const int seg = kt >> 6;
        const size_t koff = (size_t)(kt & (NSEG_KT - 1)) * 128;
        const char* A = xh_p + koff;
        const char* B = (seg == 0 ? wl_p : wh_p) + koff;
        const uint32_t st = (uint32_t)s * STAGE_BYTES;
#pragma unroll
        for (int i = 0; i < 4; i++)        // A: 128 rows
            cp16(a_dst + st + (uint32_t)i * 4096u, A + i * gstride);
#pragma unroll
        for (int i = 0; i < 4; i++)        // B: 128 rows
            cp16(b_dst + st + (uint32_t)i * 4096u, B + i * gstride);
        CP_COMMIT();
    };

    // ---- ldmatrix per-lane geometry (stage-relative) ----
    uint32_t a_rel[4], a_sw[4];
    const int a_half = lid >> 4;
#pragma unroll
    for (int mi = 0; mi < 4; mi++) {
        int row = wm * 64 + mi * 16 + (lid & 15);
        a_rel[mi] = (uint32_t)row * 128u;
        a_sw[mi] = (uint32_t)(row & 7);
    }
    uint32_t b_rel[2], b_sw[2];
    const int b_kh = (lid >> 3) & 1;
    const int b_nbl = lid >> 4;
#pragma unroll
    for (int bj = 0; bj < 2; bj++) {
        int row = wn * 32 + (bj * 2 + b_nbl) * 8 + (lid & 7);
        b_rel[bj] = A_BYTES + (uint32_t)row * 128u;
        b_sw[bj] = (uint32_t)(row & 7);
    }

    // ---- prologue: fill 2 of 3 stages ----
    load_stage(0, 0);
    load_stage(1, 1);

    for (int kt = 0; kt < NKT; kt++) {
        int s = kt % 3;
        if (kt == NKT - 1) CP_WAIT(0); else CP_WAIT(1);
        __syncthreads();

        if (kt + 2 < NKT) load_stage((kt + 2) % 3, kt + 2);

        // segment switch: fold f16 correction into the f32 accumulators
        if (kt == NSEG_KT) {
#pragma unroll
            for (int mi = 0; mi < 4; mi++)
#pragma unroll
                for (int ni = 0; ni < 4; ni++) {
                    float2 lo = __half22float2(*(__half2*)&acc_h[mi][ni][0]);
                    float2 hi = __half22float2(*(__half2*)&acc_h[mi][ni][1]);
                    acc_f[mi][ni][0] = lo.x; acc_f[mi][ni][1] = lo.y;
                    acc_f[mi][ni][2] = hi.x; acc_f[mi][ni][3] = hi.y;
                }
        }

        const uint32_t stb = sb + (uint32_t)s * STAGE_BYTES;
        if (kt < NSEG_KT) {
#pragma unroll
            for (int k16 = 0; k16 < 4; k16++) {
                uint32_t afr[4][4];
#pragma unroll
                for (int mi = 0; mi < 4; mi++) {
                    uint32_t c = (uint32_t)(k16 * 2 + a_half) ^ a_sw[mi];
                    ldsm_x4(afr[mi], stb + a_rel[mi] + c * 16u);
                }
                uint32_t bfr[4][2];
#pragma unroll
                for (int bj = 0; bj < 2; bj++) {
                    uint32_t c = (uint32_t)(k16 * 2 + b_kh) ^ b_sw[bj];
                    uint32_t r[4];
                    ldsm_x4(r, stb + b_rel[bj] + c * 16u);
                    bfr[bj * 2 + 0][0] = r[0]; bfr[bj * 2 + 0][1] = r[1];
                    bfr[bj * 2 + 1][0] = r[2]; bfr[bj * 2 + 1][1] = r[3];
                }
#pragma unroll
                for (int mi = 0; mi < 4; mi++)
#pragma unroll
                    for (int ni = 0; ni < 4; ni++)
                        mma_f16acc(acc_h[mi][ni], afr[mi], bfr[ni][0], bfr[ni][1]);
            }
        } else {
#pragma unroll
            for (int k16 = 0; k16 < 4; k16++) {
                uint32_t afr[4][4];
#pragma unroll
                for (int mi = 0; mi < 4; mi++) {
                    uint32_t c = (uint32_t)(k16 * 2 + a_half) ^ a_sw[mi];
                    ldsm_x4(afr[mi], stb + a_rel[mi] + c * 16u);
                }
                uint32_t bfr[4][2];
#pragma unroll
                for (int bj = 0; bj < 2; bj++) {
                    uint32_t c = (uint32_t)(k16 * 2 + b_kh) ^ b_sw[bj];
                    uint32_t r[4];
                    ldsm_x4(r, stb + b_rel[bj] + c * 16u);
                    bfr[bj * 2 + 0][0] = r[0]; bfr[bj * 2 + 0][1] = r[1];
                    bfr[bj * 2 + 1][0] = r[2]; bfr[bj * 2 + 1][1] = r[3];
                }
#pragma unroll
                for (int mi = 0; mi < 4; mi++)
#pragma unroll
                    for (int ni = 0; ni < 4; ni++)
                        mma_f32acc(acc_f[mi][ni], afr[mi], bfr[ni][0], bfr[ni][1]);
            }
        }
    }

    // ---- epilogue: bias + store ----
#pragma unroll
    for (int ni = 0; ni < 4; ni++) {
        const int gc = bn + wn * 32 + ni * 8 + (lid & 3) * 2;
        const float2 bv = *(const float2*)&bias[gc];
#pragma unroll
        for (int mi = 0; mi < 4; mi++) {
            const int gr = bm + wm * 64 + mi * 16 + (lid >> 2);
            float2 o0, o1;
            o0.x = acc_f[mi][ni][0] + bv.x;
            o0.y = acc_f[mi][ni][1] + bv.y;
            o1.x = acc_f[mi][ni][2] + bv.x;
            o1.y = acc_f[mi][ni][3] + bv.y;
            *(float2*)&C[(size_t)gr * N_DIM + gc] = o0;
            *(float2*)&C[(size_t)(gr + 8) * N_DIM + gc] = o1;
        }
    }
}

// ---------------------------------------------------------------------------
extern "C" void kernel_launch(void* const* d_in, const int* in_sizes, int n_in,
                              void* d_out, int out_size) {
    const float* x  = (const float*)d_in[0];   // [4,2048,4096]
    const float* w  = (const float*)d_in[1];   // [4096,4096] (out,in)
    const float* b  = (const float*)d_in[2];   // [4096]
    const float* la = (const float*)d_in[3];   // [4096,16]
    const float* lb = (const float*)d_in[4];   // [16,4096]
    float* out = (float*)d_out;

    prep_kernel<<<dim3(16384, 2), 256>>>(x, w, la, lb);

    cudaFuncSetAttribute(gemm_hmma_kernel,
                         cudaFuncAttributeMaxDynamicSharedMemorySize, SMEM_DYN);
    gemm_hmma_kernel<<<dim3(N_DIM / BN, M_DIM / BM), NTHREADS, SMEM_DYN>>>(b, out);
}

// round 14
// speedup vs baseline: 2.0026x; 2.0026x over previous
#include <cuda_runtime.h>
#include <cuda_fp16.h>
#include <stdint.h>

#define K_DIM 4096
#define N_DIM 4096
#define M_DIM 8192

#define BM 128
#define BN 128
#define BK 64                 // fp16 per k-step = 128B row
#define NKT (K_DIM / BK)      // 64
#define NTHREADS 256
#define STAGES 3
#define A_BYTES (BM * 128)    // 16384
#define B_BYTES (BN * 128)    // 16384
#define STAGE_BYTES (A_BYTES + B_BYTES)   // 32768
#define SMEM_DYN (STAGES * STAGE_BYTES + 256)

typedef unsigned long long u64;

// ---- device scratch (allocation-guard-safe) --------------------------------
__device__ __half g_xh[(size_t)M_DIM * K_DIM];
__device__ __half g_wh[(size_t)N_DIM * K_DIM];  // [n][k] : fp16(Weff^T)

__device__ __forceinline__ uint32_t smem_to_u32(const void* p) {
    uint32_t a;
    asm("{ .reg .u64 t; cvta.to.shared.u64 t, %1; cvt.u32.u64 %0, t; }"
        : "=r"(a) : "l"(p));
    return a;
}
__device__ __forceinline__ void cp16(uint32_t dst, const void* src) {
    asm volatile("cp.async.cg.shared.global [%0], [%1], 16;\n" :: "r"(dst), "l"(src));
}
#define CP_COMMIT() asm volatile("cp.async.commit_group;\n" ::: "memory")
#define CP_WAIT(n) asm volatile("cp.async.wait_group %0;\n" :: "n"(n) : "memory")

__device__ __forceinline__ void ldsm_x4(uint32_t (&r)[4], uint32_t addr) {
    asm volatile("ldmatrix.sync.aligned.m8n8.x4.shared.b16 {%0,%1,%2,%3}, [%4];"
                 : "=r"(r[0]), "=r"(r[1]), "=r"(r[2]), "=r"(r[3]) : "r"(addr));
}
__device__ __forceinline__ void mma_f32acc(float (&c)[4], const uint32_t (&a)[4],
                                           uint32_t b0, uint32_t b1) {
    asm volatile(
        "mma.sync.aligned.m16n8k16.row.col.f32.f16.f16.f32 "
        "{%0,%1,%2,%3}, {%4,%5,%6,%7}, {%8,%9}, {%0,%1,%2,%3};"
        : "+f"(c[0]), "+f"(c[1]), "+f"(c[2]), "+f"(c[3])
        : "r"(a[0]), "r"(a[1]), "r"(a[2]), "r"(a[3]), "r"(b0), "r"(b1));
}

// ---------------------------------------------------------------------------
// merged prep: grid.y==0 -> convert X to fp16; grid.y==1 -> build fp16(Weff^T)
// ---------------------------------------------------------------------------
__global__ void prep_kernel(const float* __restrict__ x,
                            const float* __restrict__ w,
                            const float* __restrict__ la,
                            const float* __restrict__ lb) {
    __shared__ float as_[32][17];
    __shared__ float bs_[16][33];
    const int tid = threadIdx.x;

    if (blockIdx.y == 0) {
        // ---- convert X -> fp16 ----
        size_t i = ((size_t)blockIdx.x * 256 + tid) * 8;
        float4 a = *(const float4*)(x + i);
        float4 b = *(const float4*)(x + i + 4);
        float v[8] = {a.x, a.y, a.z, a.w, b.x, b.y, b.z, b.w};
        union { __half h[8]; uint4 u; } H;
#pragma unroll
        for (int j = 0; j < 8; j++) H.h[j] = __float2half(v[j]);
        *(uint4*)(g_xh + i) = H.u;
        return;
    }

    // ---- build Wt[n][k] = fp16( W[n][k] + 2*sum_r A[k][r]*B[r][n] ) ----
    const int k0 = (blockIdx.x & 127) * 32;
    const int n0 = (blockIdx.x >> 7) * 32;
    const int tx = tid & 31;   // k_local
    const int ty = tid >> 5;   // 0..7
    for (int i = tid; i < 512; i += 256) {
        int kk = i >> 4, r = i & 15;
        as_[kk][r] = la[(size_t)(k0 + kk) * 16 + r];
    }
    for (int i = tid; i < 512; i += 256) {
        int r = i >> 5, nn = i & 31;
        bs_[r][nn] = lb[(size_t)r * N_DIM + (n0 + nn)];
    }
    __syncthreads();
#pragma unroll
    for (int i = 0; i < 4; i++) {
        int nl = ty + i * 8;
        float s = 0.f;
#pragma unroll
        for (int r = 0; r < 16; r++) s += as_[tx][r] * bs_[r][nl];
        size_t idx = (size_t)(n0 + nl) * K_DIM + k0 + tx;
        g_wh[idx] = __float2half(w[idx] + 2.0f * s);
    }
}

// ---------------------------------------------------------------------------
// HMMA GEMM: C = Xh@Wh^T (f32 acc) + bias
// CTA tile 128x128, 8 warps (2m x 4n), warp tile 64x32, 3-stage pipeline,
// 2 CTAs/SM.
// ---------------------------------------------------------------------------
__global__ void __launch_bounds__(NTHREADS, 2)
gemm_hmma_kernel(const float* __restrict__ bias, float* __restrict__ C) {
    extern __shared__ char smraw[];
    const uint32_t sb = (smem_to_u32(smraw) + 127u) & ~127u;

    const int tid = threadIdx.x;
    const int wid = tid >> 5;
    const int lid = tid & 31;
    const int wm = wid & 1;        // 0..1 -> 64-row slab
    const int wn = wid >> 1;       // 0..3 -> 32-col slab
    const int bm = blockIdx.y * BM;
    const int bn = blockIdx.x * BN;

    float acc[4][4][4];
#pragma unroll
    for (int i = 0; i < 4; i++)
#pragma unroll
        for (int j = 0; j < 4; j++)
#pragma unroll
            for (int q = 0; q < 4; q++) acc[i][j][q] = 0.f;

    // ---- loader geometry ----
    const int arow = tid >> 3;             // 0..31
    const int ach = tid & 7;               // chunk in 128B row
    const size_t Kb = (size_t)K_DIM * 2;   // row stride bytes
    const uint32_t dsw = (uint32_t)((ach ^ (arow & 7)) * 16);
    const uint32_t a_dst = sb + (uint32_t)arow * 128u + dsw;            // +4096*i
    const uint32_t b_dst = sb + A_BYTES + (uint32_t)arow * 128u + dsw;  // +4096*i

    const char* xh_p = (const char*)g_xh + (size_t)(bm + arow) * Kb + (size_t)ach * 16;
    const char* wh_p = (const char*)g_wh + (size_t)(bn + arow) * Kb + (size_t)ach * 16;
    const size_t gstride = 32 * Kb;        // +32 rows

    auto load_stage = [&](int s, int kt) {
        const size_t koff = (size_t)kt * 128;
        const char* A = xh_p + koff;
        const char* B = wh_p + koff;
        const uint32_t st = (uint32_t)s * STAGE_BYTES;
#pragma unroll
        for (int i = 0; i < 4; i++)        // A: 128 rows
            cp16(a_dst + st + (uint32_t)i * 4096u, A + i * gstride);
#pragma unroll
        for (int i = 0; i < 4; i++)        // B: 128 rows
            cp16(b_dst + st + (uint32_t)i * 4096u, B + i * gstride);
        CP_COMMIT();
    };

    // ---- ldmatrix per-lane geometry (stage-relative) ----
    uint32_t a_rel[4], a_sw[4];
    const int a_half = lid >> 4;
#pragma unroll
    for (int mi = 0; mi < 4; mi++) {
        int row = wm * 64 + mi * 16 + (lid & 15);
        a_rel[mi] = (uint32_t)row * 128u;
        a_sw[mi] = (uint32_t)(row & 7);
    }
    uint32_t b_rel[2], b_sw[2];
    const int b_kh = (lid >> 3) & 1;
    const int b_nbl = lid >> 4;
#pragma unroll
    for (int bj = 0; bj < 2; bj++) {
        int row = wn * 32 + (bj * 2 + b_nbl) * 8 + (lid & 7);
        b_rel[bj] = A_BYTES + (uint32_t)row * 128u;
        b_sw[bj] = (uint32_t)(row & 7);
    }

    // ---- prologue: fill 2 of 3 stages ----
    load_stage(0, 0);
    load_stage(1, 1);

    for (int kt = 0; kt < NKT; kt++) {
        int s = kt % 3;
        if (kt == NKT - 1) CP_WAIT(0); else CP_WAIT(1);
        __syncthreads();

        if (kt + 2 < NKT) load_stage((kt + 2) % 3, kt + 2);

        const uint32_t stb = sb + (uint32_t)s * STAGE_BYTES;
#pragma unroll
        for (int k16 = 0; k16 < 4; k16++) {
            uint32_t afr[4][4];
#pragma unroll
            for (int mi = 0; mi < 4; mi++) {
                uint32_t c = (uint32_t)(k16 * 2 + a_half) ^ a_sw[mi];
                ldsm_x4(afr[mi], stb + a_rel[mi] + c * 16u);
            }
            uint32_t bfr[4][2];
#pragma unroll
            for (int bj = 0; bj < 2; bj++) {
                uint32_t c = (uint32_t)(k16 * 2 + b_kh) ^ b_sw[bj];
                uint32_t r[4];
                ldsm_x4(r, stb + b_rel[bj] + c * 16u);
                bfr[bj * 2 + 0][0] = r[0]; bfr[bj * 2 + 0][1] = r[1];
                bfr[bj * 2 + 1][0] = r[2]; bfr[bj * 2 + 1][1] = r[3];
            }
#pragma unroll
            for (int mi = 0; mi < 4; mi++)
#pragma unroll
                for (int ni = 0; ni < 4; ni++)
                    mma_f32acc(acc[mi][ni], afr[mi], bfr[ni][0], bfr[ni][1]);
        }
    }

    // ---- epilogue: bias + store ----
#pragma unroll
    for (int ni = 0; ni < 4; ni++) {
        const int gc = bn + wn * 32 + ni * 8 + (lid & 3) * 2;
        const float2 bv = *(const float2*)&bias[gc];
#pragma unroll
        for (int mi = 0; mi < 4; mi++) {
            const int gr = bm + wm * 64 + mi * 16 + (lid >> 2);
            float2 o0, o1;
            o0.x = acc[mi][ni][0] + bv.x;
            o0.y = acc[mi][ni][1] + bv.y;
            o1.x = acc[mi][ni][2] + bv.x;
            o1.y = acc[mi][ni][3] + bv.y;
            *(float2*)&C[(size_t)gr * N_DIM + gc] = o0;
            *(float2*)&C[(size_t)(gr + 8) * N_DIM + gc] = o1;
        }
    }
}

// ---------------------------------------------------------------------------
extern "C" void kernel_launch(void* const* d_in, const int* in_sizes, int n_in,
                              void* d_out, int out_size) {
    const float* x  = (const float*)d_in[0];   // [4,2048,4096]
    const float* w  = (const float*)d_in[1];   // [4096,4096] (out,in)
    const float* b  = (const float*)d_in[2];   // [4096]
    const float* la = (const float*)d_in[3];   // [4096,16]
    const float* lb = (const float*)d_in[4];   // [16,4096]
    float* out = (float*)d_out;

    prep_kernel<<<dim3(16384, 2), 256>>>(x, w, la, lb);

    cudaFuncSetAttribute(gemm_hmma_kernel,
                         cudaFuncAttributeMaxDynamicSharedMemorySize, SMEM_DYN);
    gemm_hmma_kernel<<<dim3(N_DIM / BN, M_DIM / BM), NTHREADS, SMEM_DYN>>>(b, out);
}